// round 2
// baseline (speedup 1.0000x reference)
#include <cuda_runtime.h>
#include <cstdint>
#include <cstddef>

#define N0 2000000
#define N1 200000
#define N2 16384
#define E0 3200000
#define E1 262144

// Scratch (device globals: allocation-free rule)
__device__ float g_y[(size_t)N0 * 32];     // 256 MB: x @ W1l^T for all N0 nodes
__device__ float g_h[(size_t)N1 * 32];     // layer-0 output (post-relu)
__device__ float g_agg0[(size_t)N1 * 32];  // edge-summed y
__device__ float g_agg1[(size_t)N2 * 32];  // edge-summed h
__device__ float g_cnt0[N1];
__device__ float g_cnt1[N2];

typedef unsigned long long ull;

__device__ __forceinline__ ull rep2(float a) {
    ull r; asm("mov.b64 %0, {%1,%1};" : "=l"(r) : "f"(a)); return r;
}
__device__ __forceinline__ void fma2(ull& acc, ull a, ull b) {
    asm("fma.rn.f32x2 %0, %1, %2, %0;" : "+l"(acc) : "l"(a), "l"(b));
}
__device__ __forceinline__ float2 unpk(ull v) {
    float2 f; asm("mov.b64 {%0,%1}, %2;" : "=f"(f.x), "=f"(f.y) : "l"(v)); return f;
}

__device__ __forceinline__ void store_raw(float* out, size_t row, const ull* acc) {
    ulonglong2* o = reinterpret_cast<ulonglong2*>(out + row * 32);
#pragma unroll
    for (int q = 0; q < 8; ++q) {
        ulonglong2 v; v.x = acc[2 * q]; v.y = acc[2 * q + 1];
        o[q] = v;
    }
}

__device__ __forceinline__ void store_relu(float* out, const float* agg, const float* cnt,
                                           size_t row, const ull* acc) {
    float inv = 1.0f / fmaxf(cnt[row], 1.0f);
    const float4* g = reinterpret_cast<const float4*>(agg + row * 32);
    float4* o = reinterpret_cast<float4*>(out + row * 32);
#pragma unroll
    for (int q = 0; q < 8; ++q) {
        float4 a = g[q];
        float2 p0 = unpk(acc[2 * q]);
        float2 p1 = unpk(acc[2 * q + 1]);
        float4 r;
        r.x = fmaxf(fmaf(a.x, inv, p0.x), 0.f);
        r.y = fmaxf(fmaf(a.y, inv, p0.y), 0.f);
        r.z = fmaxf(fmaf(a.z, inv, p1.x), 0.f);
        r.w = fmaxf(fmaf(a.w, inv, p1.y), 0.f);
        o[q] = r;
    }
}

// out[m, 0..31] = x[m, 0..127] @ W^T  where W is [32,128] row-major.
// mode 0: store raw y.  mode 1: out = relu(acc + agg[m,:]/max(cnt[m],1))
// Tile: 512 rows/block, 256 threads, 2 rows x 32 cols per thread, FFMA2 inner loop.
__global__ void gemm32_kernel(const float* __restrict__ x, const float* __restrict__ W,
                              int M, float* __restrict__ out, int mode,
                              const float* __restrict__ agg, const float* __restrict__ cnt) {
    extern __shared__ float smem[];
    float* sW = smem;           // [128][32] : sW[k*32 + c]
    float* xs = smem + 4096;    // [32 k][513] per chunk, k-major, pad 513 (odd -> conflict-free)

    const int tid = threadIdx.x;
    const int rbase = blockIdx.x * 512;

    // Load W transposed: STS conflict-free (consecutive c), LDG strided but tiny + L2-hot.
    for (int idx = tid; idx < 4096; idx += 256) {
        int k = idx >> 5, c = idx & 31;
        sW[idx] = W[c * 128 + k];
    }

    ull acc0[16], acc1[16];
#pragma unroll
    for (int i = 0; i < 16; ++i) { acc0[i] = 0ull; acc1[i] = 0ull; }

    for (int ch = 0; ch < 4; ++ch) {
        // Stage x chunk [512 rows][32 k] into k-major smem: 512 rows * 8 float4 = 4096
        // float4 moves = 16 iterations of 256 threads. Coalesced LDG.128, scalar STS
        // at bank (4*k4 + i + r) % 32 -> 32 distinct banks per warp.
#pragma unroll
        for (int p = 0; p < 16; ++p) {
            int idx = p * 256 + tid;
            int r = idx >> 3, k4 = idx & 7;
            int gr = rbase + r;
            float4 v = make_float4(0.f, 0.f, 0.f, 0.f);
            if (gr < M)
                v = *reinterpret_cast<const float4*>(x + (size_t)gr * 128 + ch * 32 + k4 * 4);
            int kb = k4 * 4;
            xs[(kb + 0) * 513 + r] = v.x;
            xs[(kb + 1) * 513 + r] = v.y;
            xs[(kb + 2) * 513 + r] = v.z;
            xs[(kb + 3) * 513 + r] = v.w;
        }
        __syncthreads();

        const float* wch = sW + ch * 32 * 32;
#pragma unroll
        for (int k = 0; k < 32; ++k) {
            ull xa = rep2(xs[k * 513 + tid]);
            ull xb = rep2(xs[k * 513 + 256 + tid]);
            const ulonglong2* wrow = reinterpret_cast<const ulonglong2*>(wch + k * 32);
#pragma unroll
            for (int q = 0; q < 8; ++q) {
                ulonglong2 w = wrow[q];   // LDS.128, uniform address -> broadcast
                fma2(acc0[2 * q + 0], xa, w.x);
                fma2(acc0[2 * q + 1], xa, w.y);
                fma2(acc1[2 * q + 0], xb, w.x);
                fma2(acc1[2 * q + 1], xb, w.y);
            }
        }
        __syncthreads();
    }

    size_t row0 = (size_t)rbase + tid;
    size_t row1 = row0 + 256;
    if (mode == 0) {
        if (row0 < (size_t)M) store_raw(out, row0, acc0);
        if (row1 < (size_t)M) store_raw(out, row1, acc1);
    } else {
        if (row0 < (size_t)M) store_relu(out, agg, cnt, row0, acc0);
        if (row1 < (size_t)M) store_relu(out, agg, cnt, row1, acc1);
    }
}

// Edge scatter: 8 threads per edge, each moves a float4 of the 32-dim feature.
// One full 128B line gathered per edge; vector RED into L2-resident accumulator.
__global__ void scatter_kernel(const int* __restrict__ src, const int* __restrict__ dst,
                               const float* __restrict__ feat, float* __restrict__ agg,
                               float* __restrict__ cnt, int E) {
    int g = blockIdx.x * blockDim.x + threadIdx.x;
    int e = g >> 3, part = g & 7;
    if (e >= E) return;
    int s = __ldg(src + e);
    int d = __ldg(dst + e);
    float4 v = *reinterpret_cast<const float4*>(feat + (size_t)s * 32 + part * 4);
    atomicAdd(reinterpret_cast<float4*>(agg + (size_t)d * 32 + part * 4), v);
    if (part == 0) atomicAdd(cnt + d, 1.0f);
}

// Layer-1 combine: out[i,c] = (agg1[i,:]/max(cnt,1)) @ W2l^T + h[i,:] @ W2r^T,  c in [0,64)
__global__ void final_kernel(const float* __restrict__ agg1, const float* __restrict__ cnt1,
                             const float* __restrict__ h, const float* __restrict__ W2l,
                             const float* __restrict__ W2r, float* __restrict__ out) {
    __shared__ float s2l[32 * 64];  // [k][c]
    __shared__ float s2r[32 * 64];
    int tid = threadIdx.x;
    for (int idx = tid; idx < 2048; idx += 256) {
        int c = idx >> 5, k = idx & 31;
        s2l[k * 64 + c] = W2l[idx];
        s2r[k * 64 + c] = W2r[idx];
    }
    __syncthreads();
    int i = blockIdx.x * 4 + (tid >> 6);
    int c = tid & 63;
    float inv = 1.0f / fmaxf(__ldg(cnt1 + i), 1.0f);
    const float* ag = agg1 + (size_t)i * 32;
    const float* hh = h + (size_t)i * 32;
    float s = 0.f;
#pragma unroll
    for (int k = 0; k < 32; ++k)
        s = fmaf(__ldg(ag + k) * inv, s2l[k * 64 + c], fmaf(__ldg(hh + k), s2r[k * 64 + c], s));
    out[(size_t)i * 64 + c] = s;
}

extern "C" void kernel_launch(void* const* d_in, const int* in_sizes, int n_in,
                              void* d_out, int out_size) {
    const float* x   = (const float*)d_in[0];
    const float* W1l = (const float*)d_in[1];
    const float* W1r = (const float*)d_in[2];
    const float* W2l = (const float*)d_in[3];
    const float* W2r = (const float*)d_in[4];
    const int* es0   = (const int*)d_in[5];
    const int* ed0   = (const int*)d_in[6];
    const int* es1   = (const int*)d_in[7];
    const int* ed1   = (const int*)d_in[8];
    float* out = (float*)d_out;

    float *y, *h, *agg0, *agg1, *cnt0, *cnt1;
    cudaGetSymbolAddress((void**)&y,    g_y);
    cudaGetSymbolAddress((void**)&h,    g_h);
    cudaGetSymbolAddress((void**)&agg0, g_agg0);
    cudaGetSymbolAddress((void**)&agg1, g_agg1);
    cudaGetSymbolAddress((void**)&cnt0, g_cnt0);
    cudaGetSymbolAddress((void**)&cnt1, g_cnt1);

    const size_t smem_bytes = (4096 + 32 * 513) * sizeof(float);  // 82048 B
    cudaFuncSetAttribute(gemm32_kernel, cudaFuncAttributeMaxDynamicSharedMemorySize,
                         (int)smem_bytes);

    cudaMemsetAsync(agg0, 0, sizeof(float) * (size_t)N1 * 32, 0);
    cudaMemsetAsync(cnt0, 0, sizeof(float) * N1, 0);
    cudaMemsetAsync(agg1, 0, sizeof(float) * (size_t)N2 * 32, 0);
    cudaMemsetAsync(cnt1, 0, sizeof(float) * N2, 0);

    // Layer 0: y = x @ W1l^T for all source nodes
    gemm32_kernel<<<(N0 + 511) / 512, 256, smem_bytes>>>(x, W1l, N0, y, 0, nullptr, nullptr);
    // sum y over edges into agg0 + degree counts
    scatter_kernel<<<(int)(((size_t)E0 * 8 + 255) / 256), 256>>>(es0, ed0, y, agg0, cnt0, E0);
    // h = relu(agg0/cnt + x[:N1] @ W1r^T)
    gemm32_kernel<<<(N1 + 511) / 512, 256, smem_bytes>>>(x, W1r, N1, h, 1, agg0, cnt0);
    // Layer 1 aggregation over h
    scatter_kernel<<<(int)(((size_t)E1 * 8 + 255) / 256), 256>>>(es1, ed1, h, agg1, cnt1, E1);
    // final combine
    final_kernel<<<N2 / 4, 256>>>(agg1, cnt1, h, W2l, W2r, out);
}

// round 3
// speedup vs baseline: 1.3095x; 1.3095x over previous
#include <cuda_runtime.h>
#include <cstdint>
#include <cstddef>

#define N0 2000000
#define N1 200000
#define N2 16384
#define E0 3200000
#define E1 262144

// Scratch (device globals: allocation-free rule)
__device__ float g_y[(size_t)N0 * 32];     // 256 MB: x @ W1l^T for all N0 nodes
__device__ float g_h[(size_t)N1 * 32];     // layer-0 output (post-relu)
__device__ float g_agg0[(size_t)N1 * 32];  // edge-summed y
__device__ float g_agg1[(size_t)N2 * 32];  // edge-summed h
__device__ float g_cnt0[N1];
__device__ float g_cnt1[N2];

typedef unsigned long long ull;

__device__ __forceinline__ ull rep2(float a) {
    ull r; asm("mov.b64 %0, {%1,%1};" : "=l"(r) : "f"(a)); return r;
}
__device__ __forceinline__ void fma2(ull& acc, ull a, ull b) {
    asm("fma.rn.f32x2 %0, %1, %2, %0;" : "+l"(acc) : "l"(a), "l"(b));
}
__device__ __forceinline__ float2 unpk(ull v) {
    float2 f; asm("mov.b64 {%0,%1}, %2;" : "=f"(f.x), "=f"(f.y) : "l"(v)); return f;
}

__device__ __forceinline__ uint32_t smem_u32(const void* p) {
    uint32_t a;
    asm("{ .reg .u64 t; cvta.to.shared.u64 t, %1; cvt.u32.u64 %0, t; }" : "=r"(a) : "l"(p));
    return a;
}
__device__ __forceinline__ void cp16(uint32_t dst, const void* src) {
    asm volatile("cp.async.cg.shared.global [%0], [%1], 16;" :: "r"(dst), "l"(src) : "memory");
}
__device__ __forceinline__ void cp_commit() {
    asm volatile("cp.async.commit_group;" ::: "memory");
}
template <int N>
__device__ __forceinline__ void cp_wait() {
    asm volatile("cp.async.wait_group %0;" :: "n"(N) : "memory");
}

__device__ __forceinline__ void store_raw(float* out, size_t row, const ull* acc) {
    ulonglong2* o = reinterpret_cast<ulonglong2*>(out + row * 32);
#pragma unroll
    for (int q = 0; q < 8; ++q) {
        ulonglong2 v; v.x = acc[2 * q]; v.y = acc[2 * q + 1];
        o[q] = v;
    }
}

__device__ __forceinline__ void store_relu(float* out, const float* agg, const float* cnt,
                                           size_t row, const ull* acc) {
    float inv = 1.0f / fmaxf(cnt[row], 1.0f);
    const float4* g = reinterpret_cast<const float4*>(agg + row * 32);
    float4* o = reinterpret_cast<float4*>(out + row * 32);
#pragma unroll
    for (int q = 0; q < 8; ++q) {
        float4 a = g[q];
        float2 p0 = unpk(acc[2 * q]);
        float2 p1 = unpk(acc[2 * q + 1]);
        float4 r;
        r.x = fmaxf(fmaf(a.x, inv, p0.x), 0.f);
        r.y = fmaxf(fmaf(a.y, inv, p0.y), 0.f);
        r.z = fmaxf(fmaf(a.z, inv, p1.x), 0.f);
        r.w = fmaxf(fmaf(a.w, inv, p1.y), 0.f);
        o[q] = r;
    }
}

// out[m, 0..31] = x[m, 0..127] @ W^T, W is [32,128] row-major.
// 512 rows/block, 256 threads, 2 rows x 32 cols per thread, FFMA2 inner loop.
// cp.async double-buffered over 8 chunks of K=16.
// xs layout: row-major, stride 20 floats (80 B, 16B-aligned, phase-conflict-free).
#define XS_STRIDE 20
#define XS_FLOATS (512 * XS_STRIDE)

__global__ void gemm32_kernel(const float* __restrict__ x, const float* __restrict__ W,
                              int M, float* __restrict__ out, int mode,
                              const float* __restrict__ agg, const float* __restrict__ cnt) {
    extern __shared__ float smem[];
    float* sW = smem;                 // [128 k][32 c]
    float* xs0 = smem + 4096;         // buffer 0: [512 r][20]
    float* xs1 = xs0 + XS_FLOATS;     // buffer 1

    const int tid = threadIdx.x;
    const int rbase = blockIdx.x * 512;
    const uint32_t xs0_b = smem_u32(xs0);
    const uint32_t xs1_b = smem_u32(xs1);

    // W transposed into smem: sW[k*32 + c] = W[c*128 + k]
    for (int idx = tid; idx < 4096; idx += 256) {
        int k = idx >> 5, c = idx & 31;
        sW[idx] = W[c * 128 + k];
    }

    // ---- async stage of one K=16 chunk: 512 rows x 4 float4 = 2048 cp.async ----
    auto stage = [&](int ch, uint32_t dst_base) {
#pragma unroll
        for (int p = 0; p < 8; ++p) {
            int idx = p * 256 + tid;
            int r = idx >> 2, j = idx & 3;
            int gr = rbase + r; if (gr > M - 1) gr = M - 1;   // clamp (junk rows unused)
            const float* src = x + (size_t)gr * 128 + ch * 16 + j * 4;
            cp16(dst_base + (uint32_t)(r * (XS_STRIDE * 4) + j * 16), src);
        }
        cp_commit();
    };

    ull acc0[16], acc1[16];
#pragma unroll
    for (int i = 0; i < 16; ++i) { acc0[i] = 0ull; acc1[i] = 0ull; }

    stage(0, xs0_b);

    for (int ch = 0; ch < 8; ++ch) {
        const float* cur = (ch & 1) ? xs1 : xs0;
        if (ch < 7) stage(ch + 1, (ch & 1) ? xs0_b : xs1_b);
        if (ch < 7) cp_wait<1>(); else cp_wait<0>();
        __syncthreads();

#pragma unroll
        for (int k4 = 0; k4 < 4; ++k4) {
            float4 xa4 = *reinterpret_cast<const float4*>(cur + tid * XS_STRIDE + k4 * 4);
            float4 xb4 = *reinterpret_cast<const float4*>(cur + (tid + 256) * XS_STRIDE + k4 * 4);
            const float xa_s[4] = {xa4.x, xa4.y, xa4.z, xa4.w};
            const float xb_s[4] = {xb4.x, xb4.y, xb4.z, xb4.w};
#pragma unroll
            for (int i = 0; i < 4; ++i) {
                int kg = ch * 16 + k4 * 4 + i;
                ull xa = rep2(xa_s[i]);
                ull xb = rep2(xb_s[i]);
                const ulonglong2* wrow = reinterpret_cast<const ulonglong2*>(sW + kg * 32);
#pragma unroll
                for (int q = 0; q < 8; ++q) {
                    ulonglong2 w = wrow[q];   // LDS.128 uniform -> broadcast
                    fma2(acc0[2 * q + 0], xa, w.x);
                    fma2(acc0[2 * q + 1], xa, w.y);
                    fma2(acc1[2 * q + 0], xb, w.x);
                    fma2(acc1[2 * q + 1], xb, w.y);
                }
            }
        }
        __syncthreads();   // buffer reuse safe: next stage into 'cur' is 2 iters away
    }

    size_t row0 = (size_t)rbase + tid;
    size_t row1 = row0 + 256;
    if (mode == 0) {
        if (row0 < (size_t)M) store_raw(out, row0, acc0);
        if (row1 < (size_t)M) store_raw(out, row1, acc1);
    } else {
        if (row0 < (size_t)M) store_relu(out, agg, cnt, row0, acc0);
        if (row1 < (size_t)M) store_relu(out, agg, cnt, row1, acc1);
    }
}

// Edge scatter: 8 threads/edge move float4 slices; 2 independent edges per thread (MLP).
__global__ void scatter_kernel(const int* __restrict__ src, const int* __restrict__ dst,
                               const float* __restrict__ feat, float* __restrict__ agg,
                               float* __restrict__ cnt, int E) {
    int g = blockIdx.x * blockDim.x + threadIdx.x;
    int half = E >> 1;
    int e = g >> 3, part = g & 7;
    if (e >= half) return;
    int s0 = __ldg(src + e);
    int d0 = __ldg(dst + e);
    int s1 = __ldg(src + e + half);
    int d1 = __ldg(dst + e + half);
    float4 v0 = *reinterpret_cast<const float4*>(feat + (size_t)s0 * 32 + part * 4);
    float4 v1 = *reinterpret_cast<const float4*>(feat + (size_t)s1 * 32 + part * 4);
    atomicAdd(reinterpret_cast<float4*>(agg + (size_t)d0 * 32 + part * 4), v0);
    atomicAdd(reinterpret_cast<float4*>(agg + (size_t)d1 * 32 + part * 4), v1);
    if (part == 0) {
        atomicAdd(cnt + d0, 1.0f);
        atomicAdd(cnt + d1, 1.0f);
    }
}

// Layer-1 combine: out[i,c] = (agg1[i,:]/max(cnt,1)) @ W2l^T + h[i,:] @ W2r^T
__global__ void final_kernel(const float* __restrict__ agg1, const float* __restrict__ cnt1,
                             const float* __restrict__ h, const float* __restrict__ W2l,
                             const float* __restrict__ W2r, float* __restrict__ out) {
    __shared__ float s2l[32 * 64];  // [k][c]
    __shared__ float s2r[32 * 64];
    int tid = threadIdx.x;
    for (int idx = tid; idx < 2048; idx += 256) {
        int c = idx >> 5, k = idx & 31;
        s2l[k * 64 + c] = W2l[idx];
        s2r[k * 64 + c] = W2r[idx];
    }
    __syncthreads();
    int i = blockIdx.x * 4 + (tid >> 6);
    int c = tid & 63;
    float inv = 1.0f / fmaxf(__ldg(cnt1 + i), 1.0f);
    const float* ag = agg1 + (size_t)i * 32;
    const float* hh = h + (size_t)i * 32;
    float s = 0.f;
#pragma unroll
    for (int k = 0; k < 32; ++k)
        s = fmaf(__ldg(ag + k) * inv, s2l[k * 64 + c], fmaf(__ldg(hh + k), s2r[k * 64 + c], s));
    out[(size_t)i * 64 + c] = s;
}

extern "C" void kernel_launch(void* const* d_in, const int* in_sizes, int n_in,
                              void* d_out, int out_size) {
    const float* x   = (const float*)d_in[0];
    const float* W1l = (const float*)d_in[1];
    const float* W1r = (const float*)d_in[2];
    const float* W2l = (const float*)d_in[3];
    const float* W2r = (const float*)d_in[4];
    const int* es0   = (const int*)d_in[5];
    const int* ed0   = (const int*)d_in[6];
    const int* es1   = (const int*)d_in[7];
    const int* ed1   = (const int*)d_in[8];
    float* out = (float*)d_out;

    float *y, *h, *agg0, *agg1, *cnt0, *cnt1;
    cudaGetSymbolAddress((void**)&y,    g_y);
    cudaGetSymbolAddress((void**)&h,    g_h);
    cudaGetSymbolAddress((void**)&agg0, g_agg0);
    cudaGetSymbolAddress((void**)&agg1, g_agg1);
    cudaGetSymbolAddress((void**)&cnt0, g_cnt0);
    cudaGetSymbolAddress((void**)&cnt1, g_cnt1);

    const size_t smem_bytes = (4096 + 2 * XS_FLOATS) * sizeof(float);  // 16K + 80K = 98304 B
    cudaFuncSetAttribute(gemm32_kernel, cudaFuncAttributeMaxDynamicSharedMemorySize,
                         (int)smem_bytes);

    cudaMemsetAsync(agg0, 0, sizeof(float) * (size_t)N1 * 32, 0);
    cudaMemsetAsync(cnt0, 0, sizeof(float) * N1, 0);
    cudaMemsetAsync(agg1, 0, sizeof(float) * (size_t)N2 * 32, 0);
    cudaMemsetAsync(cnt1, 0, sizeof(float) * N2, 0);

    // Layer 0: y = x @ W1l^T for all source nodes
    gemm32_kernel<<<(N0 + 511) / 512, 256, smem_bytes>>>(x, W1l, N0, y, 0, nullptr, nullptr);
    // sum y over edges into agg0 + degree counts
    scatter_kernel<<<(int)(((size_t)(E0 / 2) * 8 + 255) / 256), 256>>>(es0, ed0, y, agg0, cnt0, E0);
    // h = relu(agg0/cnt + x[:N1] @ W1r^T)
    gemm32_kernel<<<(N1 + 511) / 512, 256, smem_bytes>>>(x, W1r, N1, h, 1, agg0, cnt0);
    // Layer 1 aggregation over h
    scatter_kernel<<<(int)(((size_t)(E1 / 2) * 8 + 255) / 256), 256>>>(es1, ed1, h, agg1, cnt1, E1);
    // final combine
    final_kernel<<<N2 / 4, 256>>>(agg1, cnt1, h, W2l, W2r, out);
}